// round 2
// baseline (speedup 1.0000x reference)
#include <cuda_runtime.h>
#include <cstddef>

#define N_NODES 8192
#define IN_DIM  512
#define OUT_DIM 64
#define ALPHA   0.2f

// Scratch (no allocations allowed in kernel_launch)
__device__ float g_h[N_NODES * OUT_DIM];   // h = X @ W
__device__ float g_s1[N_NODES];            // h @ a[:64]
__device__ float g_s2[N_NODES];            // h @ a[64:]

// ---------------------------------------------------------------------------
// Kernel 1: h = X @ W   (8192x512 @ 512x64)
// 128 CTAs x 256 threads; each CTA computes a 64x64 tile of h.
// Thread owns 4 rows (g+16r) x 4 cols (c*4..c*4+3).
// ---------------------------------------------------------------------------
__global__ __launch_bounds__(256) void gemm_xw_kernel(const float* __restrict__ X,
                                                      const float* __restrict__ W) {
    __shared__ float Xs[64][36];   // stride 36: bank-conflict-free, float4-alignable
    __shared__ float Ws[32][64];

    const int t  = threadIdx.x;
    const int i0 = blockIdx.x * 64;
    const int g  = t >> 4;          // 0..15
    const int c  = t & 15;          // 0..15
    const int d4 = c * 4;

    float4 acc[4];
#pragma unroll
    for (int r = 0; r < 4; r++) acc[r] = make_float4(0.f, 0.f, 0.f, 0.f);

    for (int kc = 0; kc < IN_DIM; kc += 32) {
        // stage X tile: 64 rows x 32 k = 2048 floats = 512 float4 -> 2 per thread
        {
            int row = t >> 3, col = (t & 7) * 4;   // row 0..31, col 0..28
            *(float4*)&Xs[row][col] =
                *(const float4*)&X[(size_t)(i0 + row) * IN_DIM + kc + col];
            *(float4*)&Xs[row + 32][col] =
                *(const float4*)&X[(size_t)(i0 + row + 32) * IN_DIM + kc + col];
        }
        // stage W tile: 32 k x 64 cols = 512 float4, 2 per thread
#pragma unroll
        for (int q = 0; q < 2; q++) {
            int idx = t + 256 * q;
            int row = idx >> 4, col = (idx & 15) * 4;
            *(float4*)&Ws[row][col] = *(const float4*)&W[(size_t)(kc + row) * OUT_DIM + col];
        }
        __syncthreads();
#pragma unroll
        for (int k = 0; k < 32; k++) {
            float4 wv = *(const float4*)&Ws[k][d4];
#pragma unroll
            for (int r = 0; r < 4; r++) {
                float xv = Xs[g + 16 * r][k];
                acc[r].x += xv * wv.x;
                acc[r].y += xv * wv.y;
                acc[r].z += xv * wv.z;
                acc[r].w += xv * wv.w;
            }
        }
        __syncthreads();
    }
#pragma unroll
    for (int r = 0; r < 4; r++)
        *(float4*)&g_h[(size_t)(i0 + g + 16 * r) * OUT_DIM + d4] = acc[r];
}

// ---------------------------------------------------------------------------
// Kernel 2: s1[i] = h[i,:] @ a[0:64],  s2[i] = h[i,:] @ a[64:128]
// one warp per row
// ---------------------------------------------------------------------------
__global__ __launch_bounds__(256) void score_kernel(const float* __restrict__ a) {
    int i    = blockIdx.x * 8 + (threadIdx.x >> 5);
    int lane = threadIdx.x & 31;
    float h0 = g_h[(size_t)i * OUT_DIM + lane];
    float h1 = g_h[(size_t)i * OUT_DIM + 32 + lane];
    float p1 = h0 * a[lane]      + h1 * a[lane + 32];
    float p2 = h0 * a[64 + lane] + h1 * a[96 + lane];
#pragma unroll
    for (int off = 16; off; off >>= 1) {
        p1 += __shfl_down_sync(0xffffffffu, p1, off);
        p2 += __shfl_down_sync(0xffffffffu, p2, off);
    }
    if (lane == 0) { g_s1[i] = p1; g_s2[i] = p2; }
}

// ---------------------------------------------------------------------------
// Kernel 3: fused masked-softmax attention:
//   out[i,:] = ( sum_j e_ij * h[j,:] ) / ( sum_j e_ij ),
//   e_ij = Adj[i,j] ? exp(leaky_relu(s1[i] + s2[j])) : 0
// 128 CTAs x 256 threads; CTA handles 64 rows, streams j in chunks of 64.
// Thread owns rows i = g+16r (r=0..3) and dims d = c*4..c*4+3.
// ---------------------------------------------------------------------------
__global__ __launch_bounds__(256) void attn_kernel(const int* __restrict__ Adj,
                                                   float* __restrict__ out) {
    __shared__ float h_sm[64][68];   // stride 68: float4-aligned, conflict-free
    __shared__ float E_sm[64][68];
    __shared__ float esum_sm[64];

    const int t  = threadIdx.x;
    const int i0 = blockIdx.x * 64;
    const int g  = t >> 4;          // 0..15
    const int c  = t & 15;          // 0..15
    const int d4 = c * 4;

    float s1r[4];
#pragma unroll
    for (int r = 0; r < 4; r++) s1r[r] = g_s1[i0 + g + 16 * r];

    float4 acc[4];
    float  esum[4];
#pragma unroll
    for (int r = 0; r < 4; r++) { acc[r] = make_float4(0.f, 0.f, 0.f, 0.f); esum[r] = 0.f; }

    for (int j0 = 0; j0 < N_NODES; j0 += 64) {
        // stage h tile (64x64): thread loads rows g+16r, cols d4..d4+3 (coalesced)
#pragma unroll
        for (int r = 0; r < 4; r++) {
            int row = g + 16 * r;
            *(float4*)&h_sm[row][d4] =
                *(const float4*)&g_h[(size_t)(j0 + row) * OUT_DIM + d4];
        }
        // compute E tile: rows g+16r, cols c*4..c*4+3
        float4 s2v = *(const float4*)&g_s2[j0 + d4];
#pragma unroll
        for (int r = 0; r < 4; r++) {
            int  i   = g + 16 * r;
            int4 adj = *(const int4*)&Adj[(size_t)(i0 + i) * N_NODES + j0 + d4];
            float x;
            float4 ev;
            x = s1r[r] + s2v.x; x = x > 0.f ? x : ALPHA * x; ev.x = adj.x ? __expf(x) : 0.f;
            x = s1r[r] + s2v.y; x = x > 0.f ? x : ALPHA * x; ev.y = adj.y ? __expf(x) : 0.f;
            x = s1r[r] + s2v.z; x = x > 0.f ? x : ALPHA * x; ev.z = adj.z ? __expf(x) : 0.f;
            x = s1r[r] + s2v.w; x = x > 0.f ? x : ALPHA * x; ev.w = adj.w ? __expf(x) : 0.f;
            *(float4*)&E_sm[i][d4] = ev;
            esum[r] += (ev.x + ev.y) + (ev.z + ev.w);
        }
        __syncthreads();

        // PV accumulate: acc[i][d] += E[i][jj] * h[jj][d]
#pragma unroll 4
        for (int jj = 0; jj < 64; jj += 4) {
            float ev[4][4];
#pragma unroll
            for (int r = 0; r < 4; r++)
                *(float4*)ev[r] = *(const float4*)&E_sm[g + 16 * r][jj];
#pragma unroll
            for (int u = 0; u < 4; u++) {
                float4 hv = *(const float4*)&h_sm[jj + u][d4];
#pragma unroll
                for (int r = 0; r < 4; r++) {
                    float e = ev[r][u];
                    acc[r].x += e * hv.x;
                    acc[r].y += e * hv.y;
                    acc[r].z += e * hv.z;
                    acc[r].w += e * hv.w;
                }
            }
        }
        __syncthreads();
    }

    // reduce row sums across the 16 threads sharing each row (16-lane segments)
#pragma unroll
    for (int r = 0; r < 4; r++) {
        float v = esum[r];
#pragma unroll
        for (int off = 8; off; off >>= 1) v += __shfl_down_sync(0xffffffffu, v, off, 16);
        if (c == 0) esum_sm[g + 16 * r] = v;
    }
    __syncthreads();

#pragma unroll
    for (int r = 0; r < 4; r++) {
        int   i   = g + 16 * r;
        float inv = 1.f / esum_sm[i];
        float4 o  = make_float4(acc[r].x * inv, acc[r].y * inv,
                                acc[r].z * inv, acc[r].w * inv);
        *(float4*)&out[(size_t)(i0 + i) * OUT_DIM + d4] = o;
    }
}

// ---------------------------------------------------------------------------
extern "C" void kernel_launch(void* const* d_in, const int* in_sizes, int n_in,
                              void* d_out, int out_size) {
    const float* X   = nullptr;
    const int*   Adj = nullptr;
    const float* W   = nullptr;
    const float* a   = nullptr;
    for (int k = 0; k < n_in; k++) {
        switch (in_sizes[k]) {
            case N_NODES * IN_DIM:  X   = (const float*)d_in[k]; break;
            case N_NODES * N_NODES: Adj = (const int*)d_in[k];   break; // 8192*8192 = 67108864
            case IN_DIM * OUT_DIM:  W   = (const float*)d_in[k]; break;
            case 2 * OUT_DIM:       a   = (const float*)d_in[k]; break;
        }
    }

    gemm_xw_kernel<<<N_NODES / 64, 256>>>(X, W);
    score_kernel<<<N_NODES / 8, 256>>>(a);
    attn_kernel<<<N_NODES / 64, 256>>>(Adj, (float*)d_out);
}

// round 3
// speedup vs baseline: 1.1793x; 1.1793x over previous
#include <cuda_runtime.h>
#include <cstddef>
#include <cstdint>

#define N_NODES 8192
#define IN_DIM  512
#define OUT_DIM 64
#define ALPHA   0.2f

// Scratch (no allocations allowed in kernel_launch)
__device__ float g_h[N_NODES * OUT_DIM];   // h = X @ W
__device__ float g_s1[N_NODES];            // h @ a[:64]
__device__ float g_s2[N_NODES];            // h @ a[64:]

// ---------------------------------------------------------------------------
// Kernel 1: h = X @ W   (8192x512 @ 512x64)
// ---------------------------------------------------------------------------
__global__ __launch_bounds__(256) void gemm_xw_kernel(const float* __restrict__ X,
                                                      const float* __restrict__ W) {
    __shared__ float Xs[64][36];
    __shared__ float Ws[32][64];

    const int t  = threadIdx.x;
    const int i0 = blockIdx.x * 64;
    const int g  = t >> 4;
    const int c  = t & 15;
    const int d4 = c * 4;

    float4 acc[4];
#pragma unroll
    for (int r = 0; r < 4; r++) acc[r] = make_float4(0.f, 0.f, 0.f, 0.f);

    for (int kc = 0; kc < IN_DIM; kc += 32) {
        {
            int row = t >> 3, col = (t & 7) * 4;
            *(float4*)&Xs[row][col] =
                *(const float4*)&X[(size_t)(i0 + row) * IN_DIM + kc + col];
            *(float4*)&Xs[row + 32][col] =
                *(const float4*)&X[(size_t)(i0 + row + 32) * IN_DIM + kc + col];
        }
#pragma unroll
        for (int q = 0; q < 2; q++) {
            int idx = t + 256 * q;
            int row = idx >> 4, col = (idx & 15) * 4;
            *(float4*)&Ws[row][col] = *(const float4*)&W[(size_t)(kc + row) * OUT_DIM + col];
        }
        __syncthreads();
#pragma unroll
        for (int k = 0; k < 32; k++) {
            float4 wv = *(const float4*)&Ws[k][d4];
#pragma unroll
            for (int r = 0; r < 4; r++) {
                float xv = Xs[g + 16 * r][k];
                acc[r].x += xv * wv.x;
                acc[r].y += xv * wv.y;
                acc[r].z += xv * wv.z;
                acc[r].w += xv * wv.w;
            }
        }
        __syncthreads();
    }
#pragma unroll
    for (int r = 0; r < 4; r++)
        *(float4*)&g_h[(size_t)(i0 + g + 16 * r) * OUT_DIM + d4] = acc[r];
}

// ---------------------------------------------------------------------------
// Kernel 2: s1, s2
// ---------------------------------------------------------------------------
__global__ __launch_bounds__(256) void score_kernel(const float* __restrict__ a) {
    int i    = blockIdx.x * 8 + (threadIdx.x >> 5);
    int lane = threadIdx.x & 31;
    float h0 = g_h[(size_t)i * OUT_DIM + lane];
    float h1 = g_h[(size_t)i * OUT_DIM + 32 + lane];
    float p1 = h0 * a[lane]      + h1 * a[lane + 32];
    float p2 = h0 * a[64 + lane] + h1 * a[96 + lane];
#pragma unroll
    for (int off = 16; off; off >>= 1) {
        p1 += __shfl_down_sync(0xffffffffu, p1, off);
        p2 += __shfl_down_sync(0xffffffffu, p2, off);
    }
    if (lane == 0) { g_s1[i] = p1; g_s2[i] = p2; }
}

// ---------------------------------------------------------------------------
// Kernel 3: fused masked-softmax attention on tensor cores (tf32 mma.sync).
//
// CTA: 256 threads = 8 warps, 64 i-rows. Warp w: rows (w&3)*16 .. +15,
// j-split group grp = w>>2 (group 0: chunks j0..j0+63, group 1: j0+64..+127).
// Per 8-j step each lane computes its 4 E values directly in the
// m16n8k8 A-fragment layout (E never touches SMEM), row-sums in fp32,
// and issues 8 MMAs over d (B = h^T tf32 fragments from SMEM, LDS.64 each).
// Groups merge partial C/esum via SMEM at the end.
// ---------------------------------------------------------------------------
__device__ __forceinline__ uint32_t f2tf32(float x) {
    uint32_t u;
    asm("cvt.rna.tf32.f32 %0, %1;" : "=r"(u) : "f"(x));
    return u;
}

__global__ __launch_bounds__(256) void attn_mma_kernel(const int* __restrict__ Adj,
                                                       float* __restrict__ out) {
    // B_sm: 2 groups * [s:8][n:64][l4:4][pair:2] tf32 words = 8192
    // s2_sm: 128 floats. Reduction area aliases B_sm after main loop.
    __shared__ float smem_buf[8192 + 128];
    uint32_t* B_sm  = (uint32_t*)smem_buf;
    float*    s2_sm = smem_buf + 8192;

    const int t    = threadIdx.x;
    const int lane = t & 31;
    const int wid  = t >> 5;
    const int grp  = wid >> 2;
    const int woff = (wid & 3) * 16;
    const int g    = lane >> 2;       // 0..7
    const int l4   = lane & 3;        // 0..3

    const int i0 = blockIdx.x * 64;
    const int iA = i0 + woff + g;
    const int iB = iA + 8;

    const float s1a = g_s1[iA];
    const float s1b = g_s1[iB];
    const int* rowA = Adj + (size_t)iA * N_NODES;
    const int* rowB = Adj + (size_t)iB * N_NODES;

    float c[8][4];
#pragma unroll
    for (int tl = 0; tl < 8; tl++)
#pragma unroll
        for (int k = 0; k < 4; k++) c[tl][k] = 0.f;
    float esumA = 0.f, esumB = 0.f;

    // staging indices (thread t stages h row j0+jl, 32 dims starting at dbase)
    const int jl     = t >> 1;              // 0..127
    const int dbase  = (t & 1) * 32;
    const int sg_off = (jl >> 6) * 4096 + ((jl >> 3) & 7) * 512
                     + (jl & 3) * 2 + ((jl & 7) >> 2);  // l4*2 + slot

    for (int it = 0; it < 64; it++) {
        const int j0 = it * 128;
        // ---- stage h^T (tf32, pair-packed) + s2 for both 64-j chunks ----
        {
            const float* hrow = g_h + (size_t)(j0 + jl) * OUT_DIM + dbase;
#pragma unroll
            for (int q = 0; q < 8; q++) {
                float4 v = *(const float4*)&hrow[q * 4];
                int d = dbase + q * 4;
                B_sm[sg_off + (d + 0) * 8] = f2tf32(v.x);
                B_sm[sg_off + (d + 1) * 8] = f2tf32(v.y);
                B_sm[sg_off + (d + 2) * 8] = f2tf32(v.z);
                B_sm[sg_off + (d + 3) * 8] = f2tf32(v.w);
            }
            if (t < 128) s2_sm[t] = g_s2[j0 + t];
        }
        __syncthreads();

        const uint32_t* Bb  = B_sm + grp * 4096;
        const float*    s2b = s2_sm + grp * 64;
        const int       jcb = j0 + grp * 64;

#pragma unroll
        for (int s = 0; s < 8; s++) {
            const int jj = s * 8 + l4;
            const float s20 = s2b[jj];
            const float s21 = s2b[jj + 4];
            const int j = jcb + jj;
            const int m00 = __ldg(rowA + j);
            const int m01 = __ldg(rowA + j + 4);
            const int m10 = __ldg(rowB + j);
            const int m11 = __ldg(rowB + j + 4);

            float x, e00, e01, e10, e11;
            x = s1a + s20; x = fmaxf(x, ALPHA * x); e00 = m00 ? __expf(x) : 0.f;
            x = s1b + s20; x = fmaxf(x, ALPHA * x); e10 = m10 ? __expf(x) : 0.f;
            x = s1a + s21; x = fmaxf(x, ALPHA * x); e01 = m01 ? __expf(x) : 0.f;
            x = s1b + s21; x = fmaxf(x, ALPHA * x); e11 = m11 ? __expf(x) : 0.f;
            esumA += e00 + e01;
            esumB += e10 + e11;

            const uint32_t A0 = f2tf32(e00);   // (m=g,   k=l4)
            const uint32_t A1 = f2tf32(e10);   // (m=g+8, k=l4)
            const uint32_t A2 = f2tf32(e01);   // (m=g,   k=l4+4)
            const uint32_t A3 = f2tf32(e11);   // (m=g+8, k=l4+4)

            const uint32_t* Bp = Bb + s * 512 + g * 8 + l4 * 2;
#pragma unroll
            for (int tl = 0; tl < 8; tl++) {
                uint2 b = *(const uint2*)(Bp + tl * 64);  // b0=(k=l4,n), b1=(k=l4+4,n)
                asm volatile(
                    "mma.sync.aligned.m16n8k8.row.col.f32.tf32.tf32.f32 "
                    "{%0,%1,%2,%3}, {%4,%5,%6,%7}, {%8,%9}, {%0,%1,%2,%3};"
                    : "+f"(c[tl][0]), "+f"(c[tl][1]), "+f"(c[tl][2]), "+f"(c[tl][3])
                    : "r"(A0), "r"(A1), "r"(A2), "r"(A3), "r"(b.x), "r"(b.y));
            }
        }
        __syncthreads();
    }

    // ---- merge the two j-groups (alias reduction area onto B_sm) ----
    float* red = smem_buf;  // 4 warps * 32 lanes * 34 floats = 4352
    if (grp == 1) {
        float* p = red + ((size_t)((wid - 4) * 32 + lane)) * 34;
#pragma unroll
        for (int tl = 0; tl < 8; tl++)
#pragma unroll
            for (int k = 0; k < 4; k++) p[tl * 4 + k] = c[tl][k];
        p[32] = esumA;
        p[33] = esumB;
    }
    __syncthreads();
    if (grp == 0) {
        const float* p = red + ((size_t)(wid * 32 + lane)) * 34;
#pragma unroll
        for (int tl = 0; tl < 8; tl++)
#pragma unroll
            for (int k = 0; k < 4; k++) c[tl][k] += p[tl * 4 + k];
        esumA += p[32];
        esumB += p[33];

        // row-sum: reduce over the 4 lanes (l4) sharing each row
        esumA += __shfl_xor_sync(0xffffffffu, esumA, 1);
        esumA += __shfl_xor_sync(0xffffffffu, esumA, 2);
        esumB += __shfl_xor_sync(0xffffffffu, esumB, 1);
        esumB += __shfl_xor_sync(0xffffffffu, esumB, 2);
        const float invA = 1.f / esumA;
        const float invB = 1.f / esumB;

#pragma unroll
        for (int tl = 0; tl < 8; tl++) {
            int col = tl * 8 + l4 * 2;
            *(float2*)&out[(size_t)iA * OUT_DIM + col] =
                make_float2(c[tl][0] * invA, c[tl][1] * invA);
            *(float2*)&out[(size_t)iB * OUT_DIM + col] =
                make_float2(c[tl][2] * invB, c[tl][3] * invB);
        }
    }
}

// ---------------------------------------------------------------------------
extern "C" void kernel_launch(void* const* d_in, const int* in_sizes, int n_in,
                              void* d_out, int out_size) {
    const float* X   = nullptr;
    const int*   Adj = nullptr;
    const float* W   = nullptr;
    const float* a   = nullptr;
    for (int k = 0; k < n_in; k++) {
        switch (in_sizes[k]) {
            case N_NODES * IN_DIM:  X   = (const float*)d_in[k]; break;
            case N_NODES * N_NODES: Adj = (const int*)d_in[k];   break;
            case IN_DIM * OUT_DIM:  W   = (const float*)d_in[k]; break;
            case 2 * OUT_DIM:       a   = (const float*)d_in[k]; break;
        }
    }

    gemm_xw_kernel<<<N_NODES / 64, 256>>>(X, W);
    score_kernel<<<N_NODES / 8, 256>>>(a);
    attn_mma_kernel<<<N_NODES / 64, 256>>>(Adj, (float*)d_out);
}

// round 7
// speedup vs baseline: 4.2691x; 3.6199x over previous
#include <cuda_runtime.h>
#include <cuda_bf16.h>
#include <cstddef>
#include <cstdint>

#define N_NODES 8192
#define IN_DIM  512
#define OUT_DIM 64
#define ALPHA   0.2f
#define LOG2E   1.4426950408889634f

// ---------------- scratch (no allocations allowed) ----------------
__device__ __align__(16) float          g_h [N_NODES * OUT_DIM];      // h = X @ W (f32)
__device__ __align__(16) __nv_bfloat16  g_hT[OUT_DIM * N_NODES];      // h^T, bf16
__device__ __align__(16) float          g_s1[N_NODES];
__device__ __align__(16) float          g_s2[N_NODES];
__device__ __align__(16) float          g_pD [2 * N_NODES * OUT_DIM]; // [jh][row][col]
__device__ __align__(16) float          g_pes[2 * N_NODES];           // [jh][row]

__device__ __forceinline__ uint32_t pack_bf16(float lo, float hi) {
    uint32_t r;
    asm("cvt.rn.bf16x2.f32 %0, %1, %2;" : "=r"(r) : "f"(hi), "f"(lo));
    return r;
}
__device__ __forceinline__ float ex2f(float x) {
    float r;
    asm("ex2.approx.f32 %0, %1;" : "=f"(r) : "f"(x));
    return r;
}

// ---------------------------------------------------------------------------
// Kernel 1: h = X @ W   (8192x512 @ 512x64)
// ---------------------------------------------------------------------------
__global__ __launch_bounds__(256) void gemm_xw_kernel(const float* __restrict__ X,
                                                      const float* __restrict__ W) {
    __shared__ __align__(16) float Xs[64][36];
    __shared__ __align__(16) float Ws[32][64];
    const int t = threadIdx.x, i0 = blockIdx.x * 64;
    const int g = t >> 4, c = t & 15, d4 = c * 4;
    float4 acc[4];
#pragma unroll
    for (int r = 0; r < 4; r++) acc[r] = make_float4(0.f, 0.f, 0.f, 0.f);
    for (int kc = 0; kc < IN_DIM; kc += 32) {
        int row = t >> 3, col = (t & 7) * 4;
        *(float4*)&Xs[row][col]      = *(const float4*)&X[(size_t)(i0 + row) * IN_DIM + kc + col];
        *(float4*)&Xs[row + 32][col] = *(const float4*)&X[(size_t)(i0 + row + 32) * IN_DIM + kc + col];
#pragma unroll
        for (int q = 0; q < 2; q++) {
            int idx = t + 256 * q, rw = idx >> 4, cw = (idx & 15) * 4;
            *(float4*)&Ws[rw][cw] = *(const float4*)&W[(size_t)(kc + rw) * OUT_DIM + cw];
        }
        __syncthreads();
#pragma unroll
        for (int k = 0; k < 32; k++) {
            float4 wv = *(const float4*)&Ws[k][d4];
#pragma unroll
            for (int r = 0; r < 4; r++) {
                float xv = Xs[g + 16 * r][k];
                acc[r].x += xv * wv.x; acc[r].y += xv * wv.y;
                acc[r].z += xv * wv.z; acc[r].w += xv * wv.w;
            }
        }
        __syncthreads();
    }
#pragma unroll
    for (int r = 0; r < 4; r++)
        *(float4*)&g_h[(size_t)(i0 + g + 16 * r) * OUT_DIM + d4] = acc[r];
}

// ---------------------------------------------------------------------------
// Kernel 2: SMEM transpose h -> g_hT (bf16, coalesced), plus s1/s2 scores.
// NOTE: tile stride 68 (multiple of 4) keeps float4 row loads 16-B aligned.
// ---------------------------------------------------------------------------
__global__ __launch_bounds__(256) void score_T_kernel(const float* __restrict__ a) {
    __shared__ __align__(16) float hs[64][68];
    const int t = threadIdx.x, i0 = blockIdx.x * 64;
    {
        const int r = t >> 2, c0 = (t & 3) * 16;
#pragma unroll
        for (int q = 0; q < 4; q++)
            *(float4*)&hs[r][c0 + q * 4] =
                *(const float4*)&g_h[(size_t)(i0 + r) * OUT_DIM + c0 + q * 4];
    }
    __syncthreads();
    {
        const int d = t >> 2, ibs = (t & 3) * 16;
        uint32_t* dst = (uint32_t*)g_hT + ((size_t)d * N_NODES + i0 + ibs) / 2;
#pragma unroll
        for (int k = 0; k < 8; k++)
            dst[k] = pack_bf16(hs[ibs + 2 * k][d], hs[ibs + 2 * k + 1][d]);
    }
    {
        const int w = t >> 5, lane = t & 31;
#pragma unroll
        for (int rr = 0; rr < 8; rr++) {
            const int row = w * 8 + rr;
            float v0 = hs[row][lane], v1 = hs[row][lane + 32];
            float p1 = v0 * a[lane]      + v1 * a[lane + 32];
            float p2 = v0 * a[64 + lane] + v1 * a[96 + lane];
#pragma unroll
            for (int off = 16; off; off >>= 1) {
                p1 += __shfl_down_sync(0xffffffffu, p1, off);
                p2 += __shfl_down_sync(0xffffffffu, p2, off);
            }
            if (lane == 0) { g_s1[i0 + row] = p1; g_s2[i0 + row] = p2; }
        }
    }
}

// ---------------------------------------------------------------------------
// Kernel 3: fused masked-softmax attention, bf16 mma.sync.m16n8k16.
// grid 256: blockIdx = ib*2 + jh; CTA = 64 i-rows x 4096 j (jh half).
// ---------------------------------------------------------------------------
__global__ __launch_bounds__(256, 2) void attn_bf16_kernel(const int* __restrict__ Adj) {
    __shared__ __align__(16) float smem_buf[4352];   // B_sm(4096 w) + s2(128); aliased red
    uint32_t* B_sm  = (uint32_t*)smem_buf;
    float*    s2_sm = smem_buf + 4096;

    const int t = threadIdx.x, lane = t & 31, wid = t >> 5;
    const int ib = blockIdx.x >> 1, jh = blockIdx.x & 1;
    const int i0 = ib * 64, jbase = jh * 4096;
    const int grp = wid >> 2, woff = (wid & 3) * 16;
    const int g = lane >> 2, l4 = lane & 3;
    const int iA = i0 + woff + g, iB = iA + 8;

    const float s1a = g_s1[iA] * LOG2E;
    const float s1b = g_s1[iB] * LOG2E;
    const uint32_t bitlo = 1u << l4;
    const uint32_t bithi = 16u << l4;

    float c[8][4];
#pragma unroll
    for (int tl = 0; tl < 8; tl++)
#pragma unroll
        for (int k = 0; k < 4; k++) c[tl][k] = 0.f;
    float esA = 0.f, esB = 0.f;

    const uint32_t* hT32 = (const uint32_t*)g_hT;
    const int sn = t >> 2, sq = t & 3;

    for (int ch = 0; ch < 32; ch++) {
        const int j0 = jbase + ch * 128;

        // ---- Adj masks: warp's 16 rows x its 64-j half (coalesced LDG + ballot) ----
        uint32_t mAe = 0, mAo = 0, mBe = 0, mBo = 0;
        {
            const size_t jg = (size_t)j0 + grp * 64 + 2 * lane;
            const int rowbase = i0 + woff;
#pragma unroll
            for (int r = 0; r < 16; r++) {
                int2 v = *(const int2*)(Adj + (size_t)(rowbase + r) * N_NODES + jg);
                uint32_t be = __ballot_sync(0xffffffffu, v.x != 0);
                uint32_t bo = __ballot_sync(0xffffffffu, v.y != 0);
                if (r < 8)  { if (g == r)     { mAe = be; mAo = bo; } }
                else        { if (g == r - 8) { mBe = be; mBo = bo; } }
            }
        }
        __syncthreads();

        // ---- stage B: h^T bf16 pairs in fragment order; s2 (pre-scaled) ----
#pragma unroll
        for (int cc = 0; cc < 2; cc++) {
            const int c8 = sq + cc * 4;
            const uint4* src = (const uint4*)(hT32 + (size_t)sn * (N_NODES / 2)
                                              + (size_t)(j0 + c8 * 16) / 2);
            uint4 v0 = src[0], v1 = src[1];
            uint32_t* dst = B_sm + c8 * 512 + sn * 8;
            dst[0] = v0.x; dst[2] = v0.y; dst[4] = v0.z; dst[6] = v0.w;
            dst[1] = v1.x; dst[3] = v1.y; dst[5] = v1.z; dst[7] = v1.w;
        }
        if (t < 128) s2_sm[t] = g_s2[j0 + t] * LOG2E;
        __syncthreads();

        // ---- 4 steps of 16 j: E in A-fragment regs, 8 MMAs over d ----
#pragma unroll
        for (int s = 0; s < 4; s++) {
            const float* s2p = s2_sm + grp * 64 + s * 16;
            float2 sA = *(const float2*)(s2p + 2 * l4);
            float2 sB = *(const float2*)(s2p + 2 * l4 + 8);
            const uint32_t blo = bitlo << (s * 8);
            const uint32_t bhi = bithi << (s * 8);

            float y, e00, e01, e02, e03, e10, e11, e12, e13;
            y = s1a + sA.x; y = fmaxf(y, ALPHA * y); e00 = (mAe & blo) ? ex2f(y) : 0.f;
            y = s1a + sA.y; y = fmaxf(y, ALPHA * y); e01 = (mAo & blo) ? ex2f(y) : 0.f;
            y = s1a + sB.x; y = fmaxf(y, ALPHA * y); e02 = (mAe & bhi) ? ex2f(y) : 0.f;
            y = s1a + sB.y; y = fmaxf(y, ALPHA * y); e03 = (mAo & bhi) ? ex2f(y) : 0.f;
            y = s1b + sA.x; y = fmaxf(y, ALPHA * y); e10 = (mBe & blo) ? ex2f(y) : 0.f;
            y = s1b + sA.y; y = fmaxf(y, ALPHA * y); e11 = (mBo & blo) ? ex2f(y) : 0.f;
            y = s1b + sB.x; y = fmaxf(y, ALPHA * y); e12 = (mBe & bhi) ? ex2f(y) : 0.f;
            y = s1b + sB.y; y = fmaxf(y, ALPHA * y); e13 = (mBo & bhi) ? ex2f(y) : 0.f;
            esA += (e00 + e01) + (e02 + e03);
            esB += (e10 + e11) + (e12 + e13);

            const uint32_t a0 = pack_bf16(e00, e01);
            const uint32_t a1 = pack_bf16(e10, e11);
            const uint32_t a2 = pack_bf16(e02, e03);
            const uint32_t a3 = pack_bf16(e12, e13);

            const uint32_t* Bp = B_sm + (grp * 4 + s) * 512 + g * 8 + l4 * 2;
#pragma unroll
            for (int tl = 0; tl < 8; tl++) {
                uint2 b = *(const uint2*)(Bp + tl * 64);
                asm volatile(
                    "mma.sync.aligned.m16n8k16.row.col.f32.bf16.bf16.f32 "
                    "{%0,%1,%2,%3}, {%4,%5,%6,%7}, {%8,%9}, {%0,%1,%2,%3};"
                    : "+f"(c[tl][0]), "+f"(c[tl][1]), "+f"(c[tl][2]), "+f"(c[tl][3])
                    : "r"(a0), "r"(a1), "r"(a2), "r"(a3), "r"(b.x), "r"(b.y));
            }
        }
    }

    // ---- merge grp1 into grp0 via SMEM (alias over B_sm) ----
    __syncthreads();
    float* red = smem_buf;
    if (grp == 1) {
        float* p = red + ((size_t)((wid - 4) * 32 + lane)) * 34;
#pragma unroll
        for (int tl = 0; tl < 8; tl++)
#pragma unroll
            for (int k = 0; k < 4; k++) p[tl * 4 + k] = c[tl][k];
        p[32] = esA; p[33] = esB;
    }
    __syncthreads();
    if (grp == 0) {
        const float* p = red + ((size_t)(wid * 32 + lane)) * 34;
#pragma unroll
        for (int tl = 0; tl < 8; tl++)
#pragma unroll
            for (int k = 0; k < 4; k++) c[tl][k] += p[tl * 4 + k];
        esA += p[32]; esB += p[33];

        esA += __shfl_xor_sync(0xffffffffu, esA, 1);
        esA += __shfl_xor_sync(0xffffffffu, esA, 2);
        esB += __shfl_xor_sync(0xffffffffu, esB, 1);
        esB += __shfl_xor_sync(0xffffffffu, esB, 2);
        if (l4 == 0) {
            g_pes[(size_t)jh * N_NODES + iA] = esA;
            g_pes[(size_t)jh * N_NODES + iB] = esB;
        }
        float* outA = g_pD + ((size_t)jh * N_NODES + iA) * OUT_DIM;
        float* outB = g_pD + ((size_t)jh * N_NODES + iB) * OUT_DIM;
#pragma unroll
        for (int tl = 0; tl < 8; tl++) {
            *(float2*)(outA + tl * 8 + 2 * l4) = make_float2(c[tl][0], c[tl][1]);
            *(float2*)(outB + tl * 8 + 2 * l4) = make_float2(c[tl][2], c[tl][3]);
        }
    }
}

// ---------------------------------------------------------------------------
// Kernel 4: merge j-halves and normalize. Warp per row.
// ---------------------------------------------------------------------------
__global__ __launch_bounds__(256) void merge_kernel(float* __restrict__ out) {
    const int row  = blockIdx.x * 8 + (threadIdx.x >> 5);
    const int lane = threadIdx.x & 31;
    const float inv = 1.f / (g_pes[row] + g_pes[N_NODES + row]);
    const size_t o = (size_t)row * OUT_DIM + lane * 2;
    float2 v0 = *(const float2*)(g_pD + o);
    float2 v1 = *(const float2*)(g_pD + (size_t)N_NODES * OUT_DIM + o);
    *(float2*)(out + o) = make_float2((v0.x + v1.x) * inv, (v0.y + v1.y) * inv);
}

// ---------------------------------------------------------------------------
extern "C" void kernel_launch(void* const* d_in, const int* in_sizes, int n_in,
                              void* d_out, int out_size) {
    const float* X = nullptr; const int* Adj = nullptr;
    const float* W = nullptr; const float* a = nullptr;
    for (int k = 0; k < n_in; k++) {
        switch (in_sizes[k]) {
            case N_NODES * IN_DIM:  X   = (const float*)d_in[k]; break;
            case N_NODES * N_NODES: Adj = (const int*)d_in[k];   break;
            case IN_DIM * OUT_DIM:  W   = (const float*)d_in[k]; break;
            case 2 * OUT_DIM:       a   = (const float*)d_in[k]; break;
        }
    }

    gemm_xw_kernel<<<N_NODES / 64, 256>>>(X, W);
    score_T_kernel<<<N_NODES / 64, 256>>>(a);
    attn_bf16_kernel<<<256, 256>>>(Adj);
    merge_kernel<<<N_NODES / 8, 256>>>((float*)d_out);
}